// round 14
// baseline (speedup 1.0000x reference)
#include <cuda_runtime.h>

#define NEGV (-1000000000.0f)
#define NEGH (-5.0e8f)

static constexpr int Bb   = 8;
static constexpr int Nn   = 6000;
static constexpr int Cc   = 21;
static constexpr int MAXT = 200;
static constexpr int TS   = 256;      // NMS block size
static constexpr int NW   = TS / 32;  // 8 warps
static constexpr int KCAP = 3072;     // key capacity (cnt~2857, +5 sigma)
static constexpr int NB   = 256;      // score buckets
static constexpr int KW   = TS / 32;  // survivor-matrix words per row
static constexpr int MW   = (MAXT + 31) / 32;   // 7 pre-check mask words

// ------------------------- scratch (device globals; no allocs) -------------
__device__ float  g_scores[Bb * Cc * Nn];
__device__ float  g_selval[Bb * Cc * MAXT];
__device__ float4 g_selbox[Bb * Cc * MAXT];

// ------------------------- kernel 1: scores only ---------------------------
__global__ void k_decode(const float* __restrict__ probs)
{
    int i = blockIdx.x * blockDim.x + threadIdx.x;   // (b*N + n)
    if (i >= Bb * Nn) return;
    int b = i / Nn;
    int n = i - b * Nn;

    const float* p = probs + (size_t)i * Cc;
    float pv[Cc];
#pragma unroll
    for (int c = 0; c < Cc; c++) pv[c] = p[c];
    float best = pv[0];
    int   lbl  = 0;
#pragma unroll
    for (int c = 1; c < Cc; c++) {
        if (pv[c] > best) { best = pv[c]; lbl = c; }
    }
#pragma unroll
    for (int c = 0; c < Cc; c++) {
        float sc = (lbl != 0) ? pv[c] : 0.f;
        sc = (sc > 0.5f) ? sc : NEGV;
        g_scores[(size_t)(b * Cc + c) * Nn + n] = sc;
    }
}

// ------------------------- IoU decision, mostly branch/div-free ------------
// Returns exactly (__fdiv_rn(inter,denom) > 0.5f) for the reference formula.
__device__ __forceinline__ bool iou_gt_fast(const float4 sb, const float sa,
                                            const float4 cb, const float ca)
{
    float iy1 = fmaxf(sb.x, cb.x);
    float ix1 = fmaxf(sb.y, cb.y);
    float iy2 = fminf(sb.z, cb.z);
    float ix2 = fminf(sb.w, cb.w);
    float inter = __fmul_rn(fmaxf(__fsub_rn(iy2, iy1), 0.f),
                            fmaxf(__fsub_rn(ix2, ix1), 0.f));
    float denom = __fadd_rn(__fsub_rn(__fadd_rn(sa, ca), inter), 1e-8f);
    float a2 = __fadd_rn(inter, inter);
    bool gt = a2 > __fmul_rn(denom, 1.0001f);
    bool lt = a2 < __fmul_rn(denom, 0.9999f);   // inter==0 lands here (denom>0)
    if (!gt && !lt)                              // ~1e-4 of evals: exact fallback
        gt = __fdiv_rn(inter, denom) > 0.5f;
    return gt;
}

// exact intersection test: true iff inter > 0 (same fmin/fmax ops as IoU)
__device__ __forceinline__ bool isect(const float4 a, const float4 b)
{
    return (fminf(a.z, b.z) > fmaxf(a.x, b.x)) &&
           (fminf(a.w, b.w) > fmaxf(a.y, b.y));
}

// ------------------------- kernel 2: bucket-sorted greedy NMS --------------
__global__ void __launch_bounds__(TS) k_nms(const float* __restrict__ roi,
                                            const float* __restrict__ deltas)
{
    const int c  = blockIdx.x;
    const int b  = blockIdx.y;
    const int bc = b * Cc + c;
    const float* sc_g = g_scores + (size_t)bc * Nn;

    __shared__ unsigned long long s_key[KCAP];   // (score_bits<<32)|(Nn-n)
    __shared__ int      s_hist[NB];
    __shared__ int      s_off[NB];
    __shared__ int      s_cur[NB];
    __shared__ int      s_nsel;
    __shared__ float4   s_selB[MAXT];
    __shared__ float    s_selA[MAXT];
    __shared__ float4   s_cb[TS];
    __shared__ float    s_ca[TS];
    __shared__ float    s_cs[TS];
    __shared__ int      s_wcnt[NW];
    __shared__ unsigned s_srow[TS * KW];
    __shared__ unsigned char s_rowne[TS];        // row-nonempty flag per survivor
    __shared__ unsigned s_S[KW];                 // lane-0 scan selected-set
    __shared__ short    s_selpos[MAXT];

    const int tid  = threadIdx.x;
    const int lane = tid & 31;
    const int wid  = tid >> 5;

    s_hist[tid] = 0;                             // TS == NB
    __syncthreads();

    for (int n = tid; n < Nn; n += TS) {
        float sc = sc_g[n];
        if (sc > NEGH)
            atomicAdd(&s_hist[(__float_as_uint(sc) >> 15) & 0xFF], 1);
    }
    __syncthreads();

    // inclusive suffix sum over buckets (higher bucket first)
    s_off[tid] = s_hist[tid];
    __syncthreads();
#pragma unroll
    for (int o = 1; o < NB; o <<= 1) {
        int v = s_off[tid];
        int u = (tid + o < NB) ? s_off[tid + o] : 0;
        __syncthreads();
        s_off[tid] = v + u;
        __syncthreads();
    }
    int cnt = s_off[0];
    if (cnt > KCAP) cnt = KCAP;
    {
        int exc = s_off[tid] - s_hist[tid];
        __syncthreads();
        s_off[tid] = exc;
        s_cur[tid] = exc;
    }
    __syncthreads();

    // scatter keys into bucket segments
    for (int n = tid; n < Nn; n += TS) {
        float sc = sc_g[n];
        if (sc > NEGH) {
            unsigned bits = __float_as_uint(sc);
            int bk = (bits >> 15) & 0xFF;
            int pos = atomicAdd(&s_cur[bk], 1);
            if (pos < KCAP)
                s_key[pos] = ((unsigned long long)bits << 32)
                           | (unsigned int)(Nn - n);
        }
    }
    __syncthreads();

    // in-bucket rank-permute (keys distinct)
    {
        unsigned long long kreg[(KCAP + TS - 1) / TS];
        int                dreg[(KCAP + TS - 1) / TS];
        int nk = 0;
        for (int p = tid; p < cnt; p += TS) {
            unsigned long long key = s_key[p];
            int bk = (int)(key >> 47) & 0xFF;
            int s0 = s_off[bk];
            int s1 = min(s0 + s_hist[bk], cnt);
            int rank = 0;
            for (int q = s0; q < s1; q++)
                rank += (s_key[q] > key);
            kreg[nk] = key;
            dreg[nk] = s0 + rank;
            nk++;
        }
        __syncthreads();
        for (int i = 0; i < nk; i++) s_key[dreg[i]] = kreg[i];
    }
    __syncthreads();

    float*  outv = g_selval + (size_t)bc * MAXT;
    float4* outb = g_selbox + (size_t)bc * MAXT;

    // ---- batched greedy walk over the fully sorted array ----
    int nsel = 0;
    for (int p0 = 0; p0 < cnt && nsel < MAXT; p0 += TS) {
        int p = p0 + tid;
        bool has = (p < cnt);
        float4 cb = make_float4(0.f, 0.f, 0.f, 0.f);
        float  ca = 0.f, csc = 0.f;
        if (has) {
            unsigned long long key = s_key[p];
            int n = Nn - (int)(unsigned int)(key & 0xFFFFFFFFull);
            csc = __uint_as_float((unsigned int)(key >> 32));
            // ---- fused box decode (bit-exact to reference pipeline) ----
            float4 r = *(const float4*)(roi + (size_t)(b * Nn + n) * 4);
            float ah = __fsub_rn(r.z, r.x);
            float aw = __fsub_rn(r.w, r.y);
            float cy = __fmaf_rn(0.5f, ah, r.x);
            float cx = __fmaf_rn(0.5f, aw, r.y);
            float4 d = *(const float4*)(deltas +
                         ((size_t)(b * Nn + n) * Cc + c) * 4);
            float dy = __fmul_rn(d.x, 0.1f);
            float dx = __fmul_rn(d.y, 0.1f);
            float dh = __fmul_rn(d.z, 0.2f);
            float dw = __fmul_rn(d.w, 0.2f);
            float bh  = __fmul_rn(expf(dh), ah);
            float bw  = __fmul_rn(expf(dw), aw);
            float bcy = __fmaf_rn(dy, ah, cy);
            float bcx = __fmaf_rn(dx, aw, cx);
            float y1 = __fmaf_rn(-0.5f, bh, bcy);
            float x1 = __fmaf_rn(-0.5f, bw, bcx);
            float y2 = __fadd_rn(y1, bh);
            float x2 = __fadd_rn(x1, bw);
            y1 = fminf(fmaxf(y1, 0.f), 1.f);
            x1 = fminf(fmaxf(x1, 0.f), 1.f);
            y2 = fminf(fmaxf(y2, 0.f), 1.f);
            x2 = fminf(fmaxf(x2, 0.f), 1.f);
            cb = make_float4(y1, x1, y2, x2);
            ca = __fmul_rn(fmaxf(__fsub_rn(y2, y1), 0.f),
                           fmaxf(__fsub_rn(x2, x1), 0.f));
        }

        s_rowne[tid] = 0;                        // zero flags for this batch

        // ---- two-phase pre-check vs prior selections ----
        unsigned hits[MW];
#pragma unroll
        for (int w = 0; w < MW; w++) {
            int s0 = w << 5;
            int s1 = min(nsel, s0 + 32);
            unsigned mw = 0;
            for (int s = s0; s < s1; s++)
                mw |= (unsigned)isect(s_selB[s], cb) << (s - s0);
            hits[w] = mw;
        }
        bool dead = false;
#pragma unroll
        for (int w = 0; w < MW; w++) {
            unsigned mw = hits[w];
            while (mw) {
                int s = (w << 5) + (__ffs(mw) - 1);
                mw &= mw - 1;
                dead |= iou_gt_fast(s_selB[s], s_selA[s], cb, ca);
            }
        }
        bool alive = has && !dead;

        // order-preserving compaction of batch survivors
        unsigned wm = __ballot_sync(0xffffffffu, alive);
        if (lane == 0) s_wcnt[wid] = __popc(wm);
        __syncthreads();
        int base = 0, total = 0;
#pragma unroll
        for (int w = 0; w < NW; w++) {
            int v = s_wcnt[w];
            if (w < wid) base += v;
            total += v;
        }
        if (alive) {
            int off = base + __popc(wm & ((1u << lane) - 1u));
            s_cb[off] = cb; s_ca[off] = ca; s_cs[off] = csc;
        }
        __syncthreads();

        if (total > 0) {
            // survivor suppression matrix, two-phase per word; mark
            // nonempty rows (idempotent plain store)
            int kw = (total + 31) >> 5;
            for (int item = tid; item < total * kw; item += TS) {
                int p2 = item / kw;
                int w  = item - p2 * kw;
                int q0 = w << 5;
                if (q0 < p2) {
                    float4 pb = s_cb[p2];
                    float  pa = s_ca[p2];
                    int qe = min(p2, q0 + 32);
                    unsigned hm = 0;
                    for (int q = q0; q < qe; q++)
                        hm |= (unsigned)isect(s_cb[q], pb) << (q - q0);
                    unsigned bits = 0;
                    while (hm) {
                        int q = q0 + (__ffs(hm) - 1);
                        hm &= hm - 1;
                        bits |= (unsigned)iou_gt_fast(s_cb[q], s_ca[q], pb, pa)
                                << (q - q0);
                    }
                    s_srow[item] = bits;
                    if (bits) s_rowne[p2] = 1;
                }
            }
            __syncthreads();

            // lane-0 sequential scan: no ballots/shuffles. Empty-row
            // survivors are provably selected (no earlier survivor overlaps
            // them; prior selections already cleared by pre-check).
            if (tid == 0) {
                int ns = nsel;
#pragma unroll
                for (int w = 0; w < KW; w++) s_S[w] = 0;
                for (int p2 = 0; p2 < total && ns < MAXT; p2++) {
                    bool sel = true;
                    if (s_rowne[p2]) {
                        unsigned hit = 0;
                        int wmax = (p2 + 31) >> 5;   // words covering q < p2
                        for (int w = 0; w < wmax; w++)
                            hit |= s_srow[p2 * kw + w] & s_S[w];
                        sel = (hit == 0u);
                    }
                    if (sel) {
                        s_S[p2 >> 5] |= 1u << (p2 & 31);
                        s_selpos[ns++] = (short)p2;
                    }
                }
                s_nsel = ns;
            }
            __syncthreads();

            // publish this batch's selections (parallel)
            int newsel = s_nsel;
            for (int s = nsel + tid; s < newsel; s += TS) {
                int p2 = s_selpos[s];
                float4 bb = s_cb[p2];
                outv[s]   = s_cs[p2];
                outb[s]   = bb;
                s_selB[s] = bb;
                s_selA[s] = s_ca[p2];
            }
            nsel = newsel;
        }
        __syncthreads();             // s_cb/s_srow free; s_selB visible
    }

    for (int t = nsel + tid; t < MAXT; t += TS) outv[t] = NEGV;
}

// ------------------------- kernel 3: merge 21 sorted lists -> top-200 ------
__global__ void __launch_bounds__(256) k_topk(float* __restrict__ out)
{
    const int c = blockIdx.x;
    const int b = blockIdx.y;
    __shared__ float s_val[Cc * MAXT];
    __shared__ int   s_Vc[Cc];

    const float* gv = g_selval + (size_t)b * Cc * MAXT;
    for (int j = threadIdx.x; j < Cc * MAXT; j += blockDim.x) s_val[j] = gv[j];
    __syncthreads();

    if (threadIdx.x < Cc) {
        const float* L = s_val + threadIdx.x * MAXT;
        int lo = 0, hi = MAXT;
        while (lo < hi) { int m = (lo + hi) >> 1; if (L[m] > NEGH) lo = m + 1; else hi = m; }
        s_Vc[threadIdx.x] = lo;
    }
    __syncthreads();

    float* ob = out + (size_t)b * MAXT * 4;                         // bboxes [B,200,4]
    float* ol = out + (size_t)Bb * MAXT * 4 + (size_t)b * MAXT;     // labels [B,200]
    float* os = out + (size_t)Bb * MAXT * 5 + (size_t)b * MAXT;     // scores [B,200]

    if (c == 0) {   // zero-fill tail rows once per image
        int V = 0;
#pragma unroll
        for (int cc = 0; cc < Cc; cc++) V += s_Vc[cc];
        for (int r = V + (int)threadIdx.x; r < MAXT; r += blockDim.x) {
            os[r] = 0.f; ol[r] = 0.f;
            ((float4*)ob)[r] = make_float4(0.f, 0.f, 0.f, 0.f);
        }
    }

    int t = threadIdx.x;
    if (t < s_Vc[c]) {
        float v = s_val[c * MAXT + t];
        int rank = t;
#pragma unroll 1
        for (int c2 = 0; c2 < Cc; c2++) {
            if (c2 == c) continue;
            const float* L = s_val + c2 * MAXT;
            int lo = 0, hi = s_Vc[c2];
            if (c2 < c) {
                while (lo < hi) { int m = (lo + hi) >> 1; if (L[m] >= v) lo = m + 1; else hi = m; }
            } else {
                while (lo < hi) { int m = (lo + hi) >> 1; if (L[m] >  v) lo = m + 1; else hi = m; }
            }
            rank += lo;
        }
        if (rank < MAXT) {
            os[rank] = v;
            ol[rank] = (float)c;
            ((float4*)ob)[rank] = g_selbox[(size_t)b * Cc * MAXT + c * MAXT + t];
        }
    }
}

// ------------------------- launch ------------------------------------------
extern "C" void kernel_launch(void* const* d_in, const int* in_sizes, int n_in,
                              void* d_out, int out_size)
{
    const float* roi    = (const float*)d_in[0];
    const float* deltas = (const float*)d_in[1];
    const float* probs  = (const float*)d_in[2];
    float* out = (float*)d_out;

    k_decode<<<(Bb * Nn + 255) / 256, 256>>>(probs);
    dim3 g2(Cc, Bb);
    k_nms<<<g2, TS>>>(roi, deltas);
    k_topk<<<g2, 256>>>(out);
}

// round 15
// speedup vs baseline: 1.5826x; 1.5826x over previous
#include <cuda_runtime.h>

#define NEGV (-1000000000.0f)
#define NEGH (-5.0e8f)

static constexpr int Bb   = 8;
static constexpr int Nn   = 6000;
static constexpr int Cc   = 21;
static constexpr int MAXT = 200;
static constexpr int TS   = 256;      // NMS block size
static constexpr int NW   = TS / 32;  // 8 warps
static constexpr int KCAP = 3072;     // key capacity (cnt~2857, +5 sigma)
static constexpr int NB   = 256;      // score buckets
static constexpr int KW   = TS / 32;  // survivor-matrix words per row
static constexpr int MW   = (MAXT + 31) / 32;   // 7 pre-check mask words

// ------------------------- scratch (device globals; no allocs) -------------
__device__ float  g_scores[Bb * Cc * Nn];
__device__ float  g_selval[Bb * Cc * MAXT];
__device__ float4 g_selbox[Bb * Cc * MAXT];

// ------------------------- kernel 1: scores only ---------------------------
__global__ void k_decode(const float* __restrict__ probs)
{
    int i = blockIdx.x * blockDim.x + threadIdx.x;   // (b*N + n)
    if (i >= Bb * Nn) return;
    int b = i / Nn;
    int n = i - b * Nn;

    const float* p = probs + (size_t)i * Cc;
    float pv[Cc];
#pragma unroll
    for (int c = 0; c < Cc; c++) pv[c] = p[c];
    float best = pv[0];
    int   lbl  = 0;
#pragma unroll
    for (int c = 1; c < Cc; c++) {
        if (pv[c] > best) { best = pv[c]; lbl = c; }
    }
#pragma unroll
    for (int c = 0; c < Cc; c++) {
        float sc = (lbl != 0) ? pv[c] : 0.f;
        sc = (sc > 0.5f) ? sc : NEGV;
        g_scores[(size_t)(b * Cc + c) * Nn + n] = sc;
    }
}

// ------------------------- IoU decision, mostly branch/div-free ------------
// Returns exactly (__fdiv_rn(inter,denom) > 0.5f) for the reference formula.
__device__ __forceinline__ bool iou_gt_fast(const float4 sb, const float sa,
                                            const float4 cb, const float ca)
{
    float iy1 = fmaxf(sb.x, cb.x);
    float ix1 = fmaxf(sb.y, cb.y);
    float iy2 = fminf(sb.z, cb.z);
    float ix2 = fminf(sb.w, cb.w);
    float inter = __fmul_rn(fmaxf(__fsub_rn(iy2, iy1), 0.f),
                            fmaxf(__fsub_rn(ix2, ix1), 0.f));
    float denom = __fadd_rn(__fsub_rn(__fadd_rn(sa, ca), inter), 1e-8f);
    float a2 = __fadd_rn(inter, inter);
    bool gt = a2 > __fmul_rn(denom, 1.0001f);
    bool lt = a2 < __fmul_rn(denom, 0.9999f);   // inter==0 lands here (denom>0)
    if (!gt && !lt)                              // ~1e-4 of evals: exact fallback
        gt = __fdiv_rn(inter, denom) > 0.5f;
    return gt;
}

// exact intersection test: true iff inter > 0 (same fmin/fmax ops as IoU)
__device__ __forceinline__ bool isect(const float4 a, const float4 b)
{
    return (fminf(a.z, b.z) > fmaxf(a.x, b.x)) &&
           (fminf(a.w, b.w) > fmaxf(a.y, b.y));
}

// ------------------------- kernel 2: bucket-sorted greedy NMS --------------
// __launch_bounds__(TS, 2): cap regs at 128/thread so 2 CTAs co-reside per
// SM -- the 168-block grid then runs as ~1 overlapped wave instead of 2
// serial ones.
__global__ void __launch_bounds__(TS, 2) k_nms(const float* __restrict__ roi,
                                               const float* __restrict__ deltas)
{
    const int c  = blockIdx.x;
    const int b  = blockIdx.y;
    const int bc = b * Cc + c;
    const float* sc_g = g_scores + (size_t)bc * Nn;

    __shared__ unsigned long long s_key[KCAP];   // (score_bits<<32)|(Nn-n)
    __shared__ int      s_hist[NB];
    __shared__ int      s_off[NB];
    __shared__ int      s_cur[NB];
    __shared__ int      s_nsel;
    __shared__ float4   s_selB[MAXT];
    __shared__ float    s_selA[MAXT];
    __shared__ float4   s_cb[TS];
    __shared__ float    s_ca[TS];
    __shared__ float    s_cs[TS];
    __shared__ int      s_wcnt[NW];
    __shared__ unsigned s_srow[TS * KW];
    __shared__ short    s_selpos[MAXT];

    const int tid  = threadIdx.x;
    const int lane = tid & 31;
    const int wid  = tid >> 5;

    s_hist[tid] = 0;                             // TS == NB
    __syncthreads();

    for (int n = tid; n < Nn; n += TS) {
        float sc = sc_g[n];
        if (sc > NEGH)
            atomicAdd(&s_hist[(__float_as_uint(sc) >> 15) & 0xFF], 1);
    }
    __syncthreads();

    // inclusive suffix sum over buckets (higher bucket first)
    s_off[tid] = s_hist[tid];
    __syncthreads();
#pragma unroll
    for (int o = 1; o < NB; o <<= 1) {
        int v = s_off[tid];
        int u = (tid + o < NB) ? s_off[tid + o] : 0;
        __syncthreads();
        s_off[tid] = v + u;
        __syncthreads();
    }
    int cnt = s_off[0];
    if (cnt > KCAP) cnt = KCAP;
    {
        int exc = s_off[tid] - s_hist[tid];
        __syncthreads();
        s_off[tid] = exc;
        s_cur[tid] = exc;
    }
    __syncthreads();

    // scatter keys into bucket segments
    for (int n = tid; n < Nn; n += TS) {
        float sc = sc_g[n];
        if (sc > NEGH) {
            unsigned bits = __float_as_uint(sc);
            int bk = (bits >> 15) & 0xFF;
            int pos = atomicAdd(&s_cur[bk], 1);
            if (pos < KCAP)
                s_key[pos] = ((unsigned long long)bits << 32)
                           | (unsigned int)(Nn - n);
        }
    }
    __syncthreads();

    // in-bucket rank-permute (keys distinct)
    {
        unsigned long long kreg[(KCAP + TS - 1) / TS];
        int                dreg[(KCAP + TS - 1) / TS];
        int nk = 0;
        for (int p = tid; p < cnt; p += TS) {
            unsigned long long key = s_key[p];
            int bk = (int)(key >> 47) & 0xFF;
            int s0 = s_off[bk];
            int s1 = min(s0 + s_hist[bk], cnt);
            int rank = 0;
            for (int q = s0; q < s1; q++)
                rank += (s_key[q] > key);
            kreg[nk] = key;
            dreg[nk] = s0 + rank;
            nk++;
        }
        __syncthreads();
        for (int i = 0; i < nk; i++) s_key[dreg[i]] = kreg[i];
    }
    __syncthreads();

    float*  outv = g_selval + (size_t)bc * MAXT;
    float4* outb = g_selbox + (size_t)bc * MAXT;

    // ---- batched greedy walk over the fully sorted array ----
    int nsel = 0;
    for (int p0 = 0; p0 < cnt && nsel < MAXT; p0 += TS) {
        int p = p0 + tid;
        bool has = (p < cnt);
        float4 cb = make_float4(0.f, 0.f, 0.f, 0.f);
        float  ca = 0.f, csc = 0.f;
        if (has) {
            unsigned long long key = s_key[p];
            int n = Nn - (int)(unsigned int)(key & 0xFFFFFFFFull);
            csc = __uint_as_float((unsigned int)(key >> 32));
            // ---- fused box decode (bit-exact to reference pipeline) ----
            float4 r = *(const float4*)(roi + (size_t)(b * Nn + n) * 4);
            float ah = __fsub_rn(r.z, r.x);
            float aw = __fsub_rn(r.w, r.y);
            float cy = __fmaf_rn(0.5f, ah, r.x);
            float cx = __fmaf_rn(0.5f, aw, r.y);
            float4 d = *(const float4*)(deltas +
                         ((size_t)(b * Nn + n) * Cc + c) * 4);
            float dy = __fmul_rn(d.x, 0.1f);
            float dx = __fmul_rn(d.y, 0.1f);
            float dh = __fmul_rn(d.z, 0.2f);
            float dw = __fmul_rn(d.w, 0.2f);
            float bh  = __fmul_rn(expf(dh), ah);
            float bw  = __fmul_rn(expf(dw), aw);
            float bcy = __fmaf_rn(dy, ah, cy);
            float bcx = __fmaf_rn(dx, aw, cx);
            float y1 = __fmaf_rn(-0.5f, bh, bcy);
            float x1 = __fmaf_rn(-0.5f, bw, bcx);
            float y2 = __fadd_rn(y1, bh);
            float x2 = __fadd_rn(x1, bw);
            y1 = fminf(fmaxf(y1, 0.f), 1.f);
            x1 = fminf(fmaxf(x1, 0.f), 1.f);
            y2 = fminf(fmaxf(y2, 0.f), 1.f);
            x2 = fminf(fmaxf(x2, 0.f), 1.f);
            cb = make_float4(y1, x1, y2, x2);
            ca = __fmul_rn(fmaxf(__fsub_rn(y2, y1), 0.f),
                           fmaxf(__fsub_rn(x2, x1), 0.f));
        }

        // ---- two-phase pre-check vs prior selections ----
        unsigned hits[MW];
#pragma unroll
        for (int w = 0; w < MW; w++) {
            int s0 = w << 5;
            int s1 = min(nsel, s0 + 32);
            unsigned mw = 0;
            for (int s = s0; s < s1; s++)
                mw |= (unsigned)isect(s_selB[s], cb) << (s - s0);
            hits[w] = mw;
        }
        bool dead = false;
#pragma unroll
        for (int w = 0; w < MW; w++) {
            unsigned mw = hits[w];
            while (mw) {
                int s = (w << 5) + (__ffs(mw) - 1);
                mw &= mw - 1;
                dead |= iou_gt_fast(s_selB[s], s_selA[s], cb, ca);
            }
        }
        bool alive = has && !dead;

        // order-preserving compaction of batch survivors
        unsigned wm = __ballot_sync(0xffffffffu, alive);
        if (lane == 0) s_wcnt[wid] = __popc(wm);
        __syncthreads();
        int base = 0, total = 0;
#pragma unroll
        for (int w = 0; w < NW; w++) {
            int v = s_wcnt[w];
            if (w < wid) base += v;
            total += v;
        }
        if (alive) {
            int off = base + __popc(wm & ((1u << lane) - 1u));
            s_cb[off] = cb; s_ca[off] = ca; s_cs[off] = csc;
        }
        __syncthreads();

        if (total > 0) {
            // survivor suppression matrix, two-phase per word
            int kw = (total + 31) >> 5;
            for (int item = tid; item < total * kw; item += TS) {
                int p2 = item / kw;
                int w  = item - p2 * kw;
                int q0 = w << 5;
                if (q0 < p2) {
                    float4 pb = s_cb[p2];
                    float  pa = s_ca[p2];
                    int qe = min(p2, q0 + 32);
                    unsigned hm = 0;
                    for (int q = q0; q < qe; q++)
                        hm |= (unsigned)isect(s_cb[q], pb) << (q - q0);
                    unsigned bits = 0;
                    while (hm) {
                        int q = q0 + (__ffs(hm) - 1);
                        hm &= hm - 1;
                        bits |= (unsigned)iou_gt_fast(s_cb[q], s_ca[q], pb, pa)
                                << (q - q0);
                    }
                    s_srow[item] = bits;
                }
            }
            __syncthreads();

            // warp 0: in-order scan, selected-set in lane registers
            if (wid == 0) {
                unsigned Sl = 0;
                int ns = nsel;
                for (int p2 = 0; p2 < total && ns < MAXT; p2++) {
                    bool hit = (lane < kw) &&
                               ((s_srow[p2 * kw + lane] & Sl) != 0u);
                    unsigned any = __ballot_sync(0xffffffffu, hit);
                    if (!any) {
                        if (lane == (p2 >> 5)) Sl |= 1u << (p2 & 31);
                        if (lane == 0) s_selpos[ns] = (short)p2;
                        ns++;
                    }
                }
                if (lane == 0) s_nsel = ns;
            }
            __syncthreads();

            // publish this batch's selections (parallel)
            int newsel = s_nsel;
            for (int s = nsel + tid; s < newsel; s += TS) {
                int p2 = s_selpos[s];
                float4 bb = s_cb[p2];
                outv[s]   = s_cs[p2];
                outb[s]   = bb;
                s_selB[s] = bb;
                s_selA[s] = s_ca[p2];
            }
            nsel = newsel;
        }
        __syncthreads();             // s_cb/s_srow free; s_selB visible
    }

    for (int t = nsel + tid; t < MAXT; t += TS) outv[t] = NEGV;
}

// ------------------------- kernel 3: merge 21 sorted lists -> top-200 ------
__global__ void __launch_bounds__(256) k_topk(float* __restrict__ out)
{
    const int c = blockIdx.x;
    const int b = blockIdx.y;
    __shared__ float s_val[Cc * MAXT];
    __shared__ int   s_Vc[Cc];

    const float* gv = g_selval + (size_t)b * Cc * MAXT;
    for (int j = threadIdx.x; j < Cc * MAXT; j += blockDim.x) s_val[j] = gv[j];
    __syncthreads();

    if (threadIdx.x < Cc) {
        const float* L = s_val + threadIdx.x * MAXT;
        int lo = 0, hi = MAXT;
        while (lo < hi) { int m = (lo + hi) >> 1; if (L[m] > NEGH) lo = m + 1; else hi = m; }
        s_Vc[threadIdx.x] = lo;
    }
    __syncthreads();

    float* ob = out + (size_t)b * MAXT * 4;                         // bboxes [B,200,4]
    float* ol = out + (size_t)Bb * MAXT * 4 + (size_t)b * MAXT;     // labels [B,200]
    float* os = out + (size_t)Bb * MAXT * 5 + (size_t)b * MAXT;     // scores [B,200]

    if (c == 0) {   // zero-fill tail rows once per image
        int V = 0;
#pragma unroll
        for (int cc = 0; cc < Cc; cc++) V += s_Vc[cc];
        for (int r = V + (int)threadIdx.x; r < MAXT; r += blockDim.x) {
            os[r] = 0.f; ol[r] = 0.f;
            ((float4*)ob)[r] = make_float4(0.f, 0.f, 0.f, 0.f);
        }
    }

    int t = threadIdx.x;
    if (t < s_Vc[c]) {
        float v = s_val[c * MAXT + t];
        int rank = t;
#pragma unroll 1
        for (int c2 = 0; c2 < Cc; c2++) {
            if (c2 == c) continue;
            const float* L = s_val + c2 * MAXT;
            int lo = 0, hi = s_Vc[c2];
            if (c2 < c) {
                while (lo < hi) { int m = (lo + hi) >> 1; if (L[m] >= v) lo = m + 1; else hi = m; }
            } else {
                while (lo < hi) { int m = (lo + hi) >> 1; if (L[m] >  v) lo = m + 1; else hi = m; }
            }
            rank += lo;
        }
        if (rank < MAXT) {
            os[rank] = v;
            ol[rank] = (float)c;
            ((float4*)ob)[rank] = g_selbox[(size_t)b * Cc * MAXT + c * MAXT + t];
        }
    }
}

// ------------------------- launch ------------------------------------------
extern "C" void kernel_launch(void* const* d_in, const int* in_sizes, int n_in,
                              void* d_out, int out_size)
{
    const float* roi    = (const float*)d_in[0];
    const float* deltas = (const float*)d_in[1];
    const float* probs  = (const float*)d_in[2];
    float* out = (float*)d_out;

    k_decode<<<(Bb * Nn + 255) / 256, 256>>>(probs);
    dim3 g2(Cc, Bb);
    k_nms<<<g2, TS>>>(roi, deltas);
    k_topk<<<g2, 256>>>(out);
}

// round 16
// speedup vs baseline: 1.6495x; 1.0423x over previous
#include <cuda_runtime.h>

#define NEGV (-1000000000.0f)
#define NEGH (-5.0e8f)

static constexpr int Bb   = 8;
static constexpr int Nn   = 6000;
static constexpr int Cc   = 21;
static constexpr int MAXT = 200;
static constexpr int TS   = 256;      // NMS block size
static constexpr int NW   = TS / 32;  // 8 warps
static constexpr int KCAP = 3072;     // key capacity (cnt~2857, +5 sigma)
static constexpr int NB   = 256;      // score buckets
static constexpr int KW   = TS / 32;  // survivor-matrix words per row
static constexpr int MW   = (MAXT + 31) / 32;   // 7 selection-mask words
static constexpr int GC   = 8;        // spatial grid cells per dim

// ------------------------- scratch (device globals; no allocs) -------------
__device__ float  g_scores[Bb * Cc * Nn];
__device__ float  g_selval[Bb * Cc * MAXT];
__device__ float4 g_selbox[Bb * Cc * MAXT];

// ------------------------- kernel 1: scores only ---------------------------
__global__ void k_decode(const float* __restrict__ probs)
{
    int i = blockIdx.x * blockDim.x + threadIdx.x;   // (b*N + n)
    if (i >= Bb * Nn) return;
    int b = i / Nn;
    int n = i - b * Nn;

    const float* p = probs + (size_t)i * Cc;
    float pv[Cc];
#pragma unroll
    for (int c = 0; c < Cc; c++) pv[c] = p[c];
    float best = pv[0];
    int   lbl  = 0;
#pragma unroll
    for (int c = 1; c < Cc; c++) {
        if (pv[c] > best) { best = pv[c]; lbl = c; }
    }
#pragma unroll
    for (int c = 0; c < Cc; c++) {
        float sc = (lbl != 0) ? pv[c] : 0.f;
        sc = (sc > 0.5f) ? sc : NEGV;
        g_scores[(size_t)(b * Cc + c) * Nn + n] = sc;
    }
}

// ------------------------- IoU decision, mostly branch/div-free ------------
// Returns exactly (__fdiv_rn(inter,denom) > 0.5f) for the reference formula.
__device__ __forceinline__ bool iou_gt_fast(const float4 sb, const float sa,
                                            const float4 cb, const float ca)
{
    float iy1 = fmaxf(sb.x, cb.x);
    float ix1 = fmaxf(sb.y, cb.y);
    float iy2 = fminf(sb.z, cb.z);
    float ix2 = fminf(sb.w, cb.w);
    float inter = __fmul_rn(fmaxf(__fsub_rn(iy2, iy1), 0.f),
                            fmaxf(__fsub_rn(ix2, ix1), 0.f));
    float denom = __fadd_rn(__fsub_rn(__fadd_rn(sa, ca), inter), 1e-8f);
    float a2 = __fadd_rn(inter, inter);
    bool gt = a2 > __fmul_rn(denom, 1.0001f);
    bool lt = a2 < __fmul_rn(denom, 0.9999f);   // inter==0 lands here (denom>0)
    if (!gt && !lt)                              // ~1e-4 of evals: exact fallback
        gt = __fdiv_rn(inter, denom) > 0.5f;
    return gt;
}

// exact intersection test: true iff inter > 0 (same fmin/fmax ops as IoU)
__device__ __forceinline__ bool isect(const float4 a, const float4 b)
{
    return (fminf(a.z, b.z) > fmaxf(a.x, b.x)) &&
           (fminf(a.w, b.w) > fmaxf(a.y, b.y));
}

// cell range of a clipped box (coords in [0,1])
__device__ __forceinline__ void cell_range(const float4 bb,
                                           int& cy1, int& cx1, int& cy2, int& cx2)
{
    cy1 = min(GC - 1, (int)(bb.x * (float)GC));
    cx1 = min(GC - 1, (int)(bb.y * (float)GC));
    cy2 = min(GC - 1, (int)(bb.z * (float)GC));
    cx2 = min(GC - 1, (int)(bb.w * (float)GC));
}

// ------------------------- kernel 2: bucket-sorted greedy NMS --------------
__global__ void __launch_bounds__(TS) k_nms(const float* __restrict__ roi,
                                            const float* __restrict__ deltas)
{
    const int c  = blockIdx.x;
    const int b  = blockIdx.y;
    const int bc = b * Cc + c;
    const float* sc_g = g_scores + (size_t)bc * Nn;

    __shared__ unsigned long long s_key[KCAP];   // (score_bits<<32)|(Nn-n)
    __shared__ int      s_hist[NB];
    __shared__ int      s_off[NB];
    __shared__ int      s_cur[NB];
    __shared__ int      s_nsel;
    __shared__ float4   s_selB[MAXT];
    __shared__ float    s_selA[MAXT];
    __shared__ float4   s_cb[TS];
    __shared__ float    s_ca[TS];
    __shared__ float    s_cs[TS];
    __shared__ int      s_wcnt[NW];
    __shared__ unsigned s_srow[TS * KW];
    __shared__ unsigned s_cell[GC * GC][MW];     // per-cell selected-box masks
    __shared__ short    s_selpos[MAXT];

    const int tid  = threadIdx.x;
    const int lane = tid & 31;
    const int wid  = tid >> 5;

    s_hist[tid] = 0;                             // TS == NB
    for (int i = tid; i < GC * GC * MW; i += TS)
        ((unsigned*)s_cell)[i] = 0u;
    __syncthreads();

    for (int n = tid; n < Nn; n += TS) {
        float sc = sc_g[n];
        if (sc > NEGH)
            atomicAdd(&s_hist[(__float_as_uint(sc) >> 15) & 0xFF], 1);
    }
    __syncthreads();

    // inclusive suffix sum over buckets (higher bucket first)
    s_off[tid] = s_hist[tid];
    __syncthreads();
#pragma unroll
    for (int o = 1; o < NB; o <<= 1) {
        int v = s_off[tid];
        int u = (tid + o < NB) ? s_off[tid + o] : 0;
        __syncthreads();
        s_off[tid] = v + u;
        __syncthreads();
    }
    int cnt = s_off[0];
    if (cnt > KCAP) cnt = KCAP;
    {
        int exc = s_off[tid] - s_hist[tid];
        __syncthreads();
        s_off[tid] = exc;
        s_cur[tid] = exc;
    }
    __syncthreads();

    // scatter keys into bucket segments
    for (int n = tid; n < Nn; n += TS) {
        float sc = sc_g[n];
        if (sc > NEGH) {
            unsigned bits = __float_as_uint(sc);
            int bk = (bits >> 15) & 0xFF;
            int pos = atomicAdd(&s_cur[bk], 1);
            if (pos < KCAP)
                s_key[pos] = ((unsigned long long)bits << 32)
                           | (unsigned int)(Nn - n);
        }
    }
    __syncthreads();

    // in-bucket rank-permute (keys distinct)
    {
        unsigned long long kreg[(KCAP + TS - 1) / TS];
        int                dreg[(KCAP + TS - 1) / TS];
        int nk = 0;
        for (int p = tid; p < cnt; p += TS) {
            unsigned long long key = s_key[p];
            int bk = (int)(key >> 47) & 0xFF;
            int s0 = s_off[bk];
            int s1 = min(s0 + s_hist[bk], cnt);
            int rank = 0;
            for (int q = s0; q < s1; q++)
                rank += (s_key[q] > key);
            kreg[nk] = key;
            dreg[nk] = s0 + rank;
            nk++;
        }
        __syncthreads();
        for (int i = 0; i < nk; i++) s_key[dreg[i]] = kreg[i];
    }
    __syncthreads();

    float*  outv = g_selval + (size_t)bc * MAXT;
    float4* outb = g_selbox + (size_t)bc * MAXT;

    // ---- batched greedy walk over the fully sorted array ----
    int nsel = 0;
    for (int p0 = 0; p0 < cnt && nsel < MAXT; p0 += TS) {
        int p = p0 + tid;
        bool has = (p < cnt);
        float4 cb = make_float4(0.f, 0.f, 0.f, 0.f);
        float  ca = 0.f, csc = 0.f;
        if (has) {
            unsigned long long key = s_key[p];
            int n = Nn - (int)(unsigned int)(key & 0xFFFFFFFFull);
            csc = __uint_as_float((unsigned int)(key >> 32));
            // ---- fused box decode (bit-exact to reference pipeline) ----
            float4 r = *(const float4*)(roi + (size_t)(b * Nn + n) * 4);
            float ah = __fsub_rn(r.z, r.x);
            float aw = __fsub_rn(r.w, r.y);
            float cy = __fmaf_rn(0.5f, ah, r.x);
            float cx = __fmaf_rn(0.5f, aw, r.y);
            float4 d = *(const float4*)(deltas +
                         ((size_t)(b * Nn + n) * Cc + c) * 4);
            float dy = __fmul_rn(d.x, 0.1f);
            float dx = __fmul_rn(d.y, 0.1f);
            float dh = __fmul_rn(d.z, 0.2f);
            float dw = __fmul_rn(d.w, 0.2f);
            float bh  = __fmul_rn(expf(dh), ah);
            float bw  = __fmul_rn(expf(dw), aw);
            float bcy = __fmaf_rn(dy, ah, cy);
            float bcx = __fmaf_rn(dx, aw, cx);
            float y1 = __fmaf_rn(-0.5f, bh, bcy);
            float x1 = __fmaf_rn(-0.5f, bw, bcx);
            float y2 = __fadd_rn(y1, bh);
            float x2 = __fadd_rn(x1, bw);
            y1 = fminf(fmaxf(y1, 0.f), 1.f);
            x1 = fminf(fmaxf(x1, 0.f), 1.f);
            y2 = fminf(fmaxf(y2, 0.f), 1.f);
            x2 = fminf(fmaxf(x2, 0.f), 1.f);
            cb = make_float4(y1, x1, y2, x2);
            ca = __fmul_rn(fmaxf(__fsub_rn(y2, y1), 0.f),
                           fmaxf(__fsub_rn(x2, x1), 0.f));
        }

        // ---- cell-filtered pre-check vs prior selections ----
        // OR masks of the candidate's covered cells -> superset of selections
        // whose boxes can intersect cb; sparse isect refine; exact IoU last.
        bool dead = false;
        if (has && nsel > 0) {
            int cy1, cx1, cy2, cx2;
            cell_range(cb, cy1, cx1, cy2, cx2);
            unsigned m[MW];
#pragma unroll
            for (int w = 0; w < MW; w++) m[w] = 0u;
            for (int yy = cy1; yy <= cy2; yy++)
                for (int xx = cx1; xx <= cx2; xx++) {
                    const unsigned* cw = s_cell[yy * GC + xx];
#pragma unroll
                    for (int w = 0; w < MW; w++) m[w] |= cw[w];
                }
#pragma unroll
            for (int w = 0; w < MW; w++) {
                unsigned mw = m[w];
                while (mw) {
                    int s = (w << 5) + (__ffs(mw) - 1);
                    mw &= mw - 1;
                    if (isect(s_selB[s], cb))
                        dead |= iou_gt_fast(s_selB[s], s_selA[s], cb, ca);
                }
            }
        }
        bool alive = has && !dead;

        // order-preserving compaction of batch survivors
        unsigned wm = __ballot_sync(0xffffffffu, alive);
        if (lane == 0) s_wcnt[wid] = __popc(wm);
        __syncthreads();
        int base = 0, total = 0;
#pragma unroll
        for (int w = 0; w < NW; w++) {
            int v = s_wcnt[w];
            if (w < wid) base += v;
            total += v;
        }
        if (alive) {
            int off = base + __popc(wm & ((1u << lane) - 1u));
            s_cb[off] = cb; s_ca[off] = ca; s_cs[off] = csc;
        }
        __syncthreads();

        if (total > 0) {
            // survivor suppression matrix, two-phase per word
            int kw = (total + 31) >> 5;
            for (int item = tid; item < total * kw; item += TS) {
                int p2 = item / kw;
                int w  = item - p2 * kw;
                int q0 = w << 5;
                if (q0 < p2) {
                    float4 pb = s_cb[p2];
                    float  pa = s_ca[p2];
                    int qe = min(p2, q0 + 32);
                    unsigned hm = 0;
                    for (int q = q0; q < qe; q++)
                        hm |= (unsigned)isect(s_cb[q], pb) << (q - q0);
                    unsigned bits = 0;
                    while (hm) {
                        int q = q0 + (__ffs(hm) - 1);
                        hm &= hm - 1;
                        bits |= (unsigned)iou_gt_fast(s_cb[q], s_ca[q], pb, pa)
                                << (q - q0);
                    }
                    s_srow[item] = bits;
                }
            }
            __syncthreads();

            // warp 0: in-order scan, selected-set in lane registers
            if (wid == 0) {
                unsigned Sl = 0;
                int ns = nsel;
                for (int p2 = 0; p2 < total && ns < MAXT; p2++) {
                    bool hit = (lane < kw) &&
                               ((s_srow[p2 * kw + lane] & Sl) != 0u);
                    unsigned any = __ballot_sync(0xffffffffu, hit);
                    if (!any) {
                        if (lane == (p2 >> 5)) Sl |= 1u << (p2 & 31);
                        if (lane == 0) s_selpos[ns] = (short)p2;
                        ns++;
                    }
                }
                if (lane == 0) s_nsel = ns;
            }
            __syncthreads();

            // publish this batch's selections + register in cell masks
            int newsel = s_nsel;
            for (int s = nsel + tid; s < newsel; s += TS) {
                int p2 = s_selpos[s];
                float4 bb = s_cb[p2];
                outv[s]   = s_cs[p2];
                outb[s]   = bb;
                s_selB[s] = bb;
                s_selA[s] = s_ca[p2];
                int cy1, cx1, cy2, cx2;
                cell_range(bb, cy1, cx1, cy2, cx2);
                unsigned bit = 1u << (s & 31);
                int w = s >> 5;
                for (int yy = cy1; yy <= cy2; yy++)
                    for (int xx = cx1; xx <= cx2; xx++)
                        atomicOr(&s_cell[yy * GC + xx][w], bit);
            }
            nsel = newsel;
        }
        __syncthreads();             // s_cb/s_srow free; s_selB/s_cell visible
    }

    for (int t = nsel + tid; t < MAXT; t += TS) outv[t] = NEGV;
}

// ------------------------- kernel 3: merge 21 sorted lists -> top-200 ------
__global__ void __launch_bounds__(256) k_topk(float* __restrict__ out)
{
    const int c = blockIdx.x;
    const int b = blockIdx.y;
    __shared__ float s_val[Cc * MAXT];
    __shared__ int   s_Vc[Cc];

    const float* gv = g_selval + (size_t)b * Cc * MAXT;
    for (int j = threadIdx.x; j < Cc * MAXT; j += blockDim.x) s_val[j] = gv[j];
    __syncthreads();

    if (threadIdx.x < Cc) {
        const float* L = s_val + threadIdx.x * MAXT;
        int lo = 0, hi = MAXT;
        while (lo < hi) { int m = (lo + hi) >> 1; if (L[m] > NEGH) lo = m + 1; else hi = m; }
        s_Vc[threadIdx.x] = lo;
    }
    __syncthreads();

    float* ob = out + (size_t)b * MAXT * 4;                         // bboxes [B,200,4]
    float* ol = out + (size_t)Bb * MAXT * 4 + (size_t)b * MAXT;     // labels [B,200]
    float* os = out + (size_t)Bb * MAXT * 5 + (size_t)b * MAXT;     // scores [B,200]

    if (c == 0) {   // zero-fill tail rows once per image
        int V = 0;
#pragma unroll
        for (int cc = 0; cc < Cc; cc++) V += s_Vc[cc];
        for (int r = V + (int)threadIdx.x; r < MAXT; r += blockDim.x) {
            os[r] = 0.f; ol[r] = 0.f;
            ((float4*)ob)[r] = make_float4(0.f, 0.f, 0.f, 0.f);
        }
    }

    int t = threadIdx.x;
    if (t < s_Vc[c]) {
        float v = s_val[c * MAXT + t];
        int rank = t;
#pragma unroll 1
        for (int c2 = 0; c2 < Cc; c2++) {
            if (c2 == c) continue;
            const float* L = s_val + c2 * MAXT;
            int lo = 0, hi = s_Vc[c2];
            if (c2 < c) {
                while (lo < hi) { int m = (lo + hi) >> 1; if (L[m] >= v) lo = m + 1; else hi = m; }
            } else {
                while (lo < hi) { int m = (lo + hi) >> 1; if (L[m] >  v) lo = m + 1; else hi = m; }
            }
            rank += lo;
        }
        if (rank < MAXT) {
            os[rank] = v;
            ol[rank] = (float)c;
            ((float4*)ob)[rank] = g_selbox[(size_t)b * Cc * MAXT + c * MAXT + t];
        }
    }
}

// ------------------------- launch ------------------------------------------
extern "C" void kernel_launch(void* const* d_in, const int* in_sizes, int n_in,
                              void* d_out, int out_size)
{
    const float* roi    = (const float*)d_in[0];
    const float* deltas = (const float*)d_in[1];
    const float* probs  = (const float*)d_in[2];
    float* out = (float*)d_out;

    k_decode<<<(Bb * Nn + 255) / 256, 256>>>(probs);
    dim3 g2(Cc, Bb);
    k_nms<<<g2, TS>>>(roi, deltas);
    k_topk<<<g2, 256>>>(out);
}